// round 14
// baseline (speedup 1.0000x reference)
#include <cuda_runtime.h>
#include <cuda_bf16.h>
#include <cstdint>

// ---------------- problem constants ----------------
#define NN 131072
#define EE 524288
#define DD 100
#define TD 300
#define DA 50
#define DC 30
#define ND (NN*DD)          // 13,107,200
#define PGRID 304           // persistent grid (2 CTAs/SM on 152-SM GB300)

// ---------------- scratch (static device globals; no allocation) ----------------
__device__ float g_h[ND];
__device__ float g_fm[ND];
__device__ float g_WT[4][30000];   // pre-transposed [d][j] GRU weights: fWih,fWhh,bWih,bWhh

// CSR scratch (edges constant -> build once per launch)
__device__ int g_degF[NN], g_degB[NN];
__device__ int g_rpF[NN], g_rpB[NN];
__device__ int g_fillF[NN], g_fillB[NN];
__device__ int g_eF[EE], g_eB[EE];
__device__ int g_bsum[256];

// ---------------- f32x2 packed-FMA helpers (sm_103a FFMA2 path) ----------------
typedef unsigned long long u64;

__device__ __forceinline__ u64 ffma2(u64 a, u64 b, u64 c) {
    u64 d;
    asm("fma.rn.f32x2 %0, %1, %2, %3;" : "=l"(d) : "l"(a), "l"(b), "l"(c));
    return d;
}
__device__ __forceinline__ u64 dup2(float x) {
    u64 d;
    asm("mov.b64 %0, {%1, %1};" : "=l"(d) : "f"(x));
    return d;
}
__device__ __forceinline__ u64 pk2(float a, float b) {
    u64 d;
    asm("mov.b64 %0, {%1, %2};" : "=l"(d) : "f"(a), "f"(b));
    return d;
}
__device__ __forceinline__ float2 unpk(u64 a) {
    float2 r;
    asm("mov.b64 {%0, %1}, %2;" : "=f"(r.x), "=f"(r.y) : "l"(a));
    return r;
}
__device__ __forceinline__ float sigf(float v) {
    return 1.0f / (1.0f + __expf(-v));
}
__device__ __forceinline__ uint32_t smem_u32(const void* p) {
    uint32_t a;
    asm("{ .reg .u64 t; cvta.to.shared.u64 t, %1; cvt.u32.u64 %0, t; }" : "=r"(a) : "l"(p));
    return a;
}
__device__ __forceinline__ void cpa16(uint32_t saddr, const void* g) {
    asm volatile("cp.async.cg.shared.global [%0], [%1], 16;" :: "r"(saddr), "l"(g));
}
#define CPA_COMMIT() asm volatile("cp.async.commit_group;" ::: "memory")
#define CPA_WAIT1()  asm volatile("cp.async.wait_group 1;" ::: "memory")

// ---------------- init: h = features @ init_W + init_b ----------------
__global__ void init_kernel(const float* __restrict__ feat,
                            const float* __restrict__ W,
                            const float* __restrict__ b) {
    int i = blockIdx.x * blockDim.x + threadIdx.x;
    if (i >= ND) return;
    int n = i / DD;
    int d = i - n * DD;
    float f0 = feat[n * 4 + 0], f1 = feat[n * 4 + 1];
    float f2 = feat[n * 4 + 2], f3 = feat[n * 4 + 3];
    g_h[i] = b[d] + f0 * W[d] + f1 * W[DD + d] + f2 * W[2 * DD + d] + f3 * W[3 * DD + d];
}

// ---------------- one-time weight transpose: g_WT[m][d*300+j] = W[j*100+d] ----------------
__global__ void transpose_w_kernel(const float* __restrict__ A, const float* __restrict__ B,
                                   const float* __restrict__ C, const float* __restrict__ E) {
    int i = blockIdx.x * blockDim.x + threadIdx.x;
    if (i >= 30000) return;
    int d = i / TD, j = i - d * TD;
    int src = j * DD + d;
    g_WT[0][i] = A[src];
    g_WT[1][i] = B[src];
    g_WT[2][i] = C[src];
    g_WT[3][i] = E[src];
}

// ---------------- CSR build kernels ----------------
__global__ void zero_deg_kernel() {
    int i = blockIdx.x * blockDim.x + threadIdx.x;
    g_degF[i] = 0;
    g_degB[i] = 0;
}
__global__ void count_deg_kernel(const int* __restrict__ row, const int* __restrict__ col) {
    int e = blockIdx.x * blockDim.x + threadIdx.x;
    atomicAdd(&g_degF[row[e]], 1);
    atomicAdd(&g_degB[col[e]], 1);
}
__global__ void scan1_kernel() {
    __shared__ int s[1024];
    int b = blockIdx.x;
    const int* deg = (b < 128) ? g_degF : g_degB;
    int* rp = (b < 128) ? g_rpF : g_rpB;
    int base = (b & 127) * 1024;
    for (int i = threadIdx.x; i < 1024; i += blockDim.x) s[i] = deg[base + i];
    __syncthreads();
    if (threadIdx.x == 0) {
        int run = 0;
        for (int i = 0; i < 1024; i++) { int v = s[i]; s[i] = run; run += v; }
        g_bsum[b] = run;
    }
    __syncthreads();
    for (int i = threadIdx.x; i < 1024; i += blockDim.x) rp[base + i] = s[i];
}
__global__ void scan2_kernel() {
    int t = threadIdx.x;
    int base = t * 128;
    int run = 0;
    for (int i = 0; i < 128; i++) { int v = g_bsum[base + i]; g_bsum[base + i] = run; run += v; }
}
__global__ void scan3_kernel() {
    int i = blockIdx.x * blockDim.x + threadIdx.x;
    if (i < NN) {
        int v = g_rpF[i] + g_bsum[i >> 10];
        g_rpF[i] = v; g_fillF[i] = v;
    } else {
        int j = i - NN;
        int v = g_rpB[j] + g_bsum[128 + (j >> 10)];
        g_rpB[j] = v; g_fillB[j] = v;
    }
}
__global__ void fill_csr_kernel(const int* __restrict__ row, const int* __restrict__ col) {
    int e = blockIdx.x * blockDim.x + threadIdx.x;
    int r = row[e], c = col[e];
    int pF = atomicAdd(&g_fillF[r], 1);
    g_eF[pF] = c;
    int pB = atomicAdd(&g_fillB[c], 1);
    g_eB[pB] = r;
}

// ---------------- persistent MLP (R10 passing form) ----------------
#define MLP_THREADS 256
#define MLP_NODES 64
#define HID 52
#define MLP_SMEM_FLOATS 26492

__global__ void __launch_bounds__(MLP_THREADS, 2)
mlp_kernel(const float* __restrict__ W1, const float* __restrict__ b1,
           const float* __restrict__ W2, const float* __restrict__ b2) {
    extern __shared__ float smem[];
    float* s_w1 = smem;
    float* s_w2 = smem + 5000;
    float* s_hid = smem + 10200;
    float* s_b2 = smem + 13528;
    float* s_b1 = smem + 13628;
    float* xb[2] = {smem + 13692, smem + 20092};
    uint32_t xaddr[2] = {smem_u32(xb[0]), smem_u32(xb[1])};

    int tid = threadIdx.x;
    int warp = tid >> 5, lane = tid & 31;
    int nb = warp * 8;
    int k0 = 4 * lane;
    bool act = lane < 25;
    const int NTILES = NN / MLP_NODES;   // 2048

#pragma unroll 1
    for (int i = tid; i < 1600; i += MLP_THREADS)
        cpa16(xaddr[0] + (uint32_t)i * 16u,
              (const void*)(((const float4*)g_h) + (size_t)blockIdx.x * 1600 + i));
    CPA_COMMIT();

    for (int i = tid; i < 5000; i += MLP_THREADS) s_w1[i] = W1[i];
    for (int i = tid; i < HID * DD; i += MLP_THREADS) s_w2[i] = (i < 5000) ? W2[i] : 0.f;
    if (tid < DD) s_b2[tid] = b2[tid];
    if (tid < DA) s_b1[tid] = b1[tid];
    if (lane == 25) {
#pragma unroll
        for (int nn = 0; nn < 8; nn++)
            *(float2*)&s_hid[(nb + nn) * HID + 50] = make_float2(0.f, 0.f);
    }

    int cur = 0;
#pragma unroll 1
    for (int tile = blockIdx.x; tile < NTILES; tile += PGRID) {
        int ntile = tile + PGRID;
        if (ntile < NTILES) {
#pragma unroll 1
            for (int i = tid; i < 1600; i += MLP_THREADS)
                cpa16(xaddr[cur ^ 1] + (uint32_t)i * 16u,
                      (const void*)(((const float4*)g_h) + (size_t)ntile * 1600 + i));
        }
        CPA_COMMIT();
        CPA_WAIT1();
        __syncthreads();

        int base = tile * MLP_NODES;
        const float* s_h = xb[cur];

        if (act) {
            int j0 = 2 * lane;
            u64 bias = pk2(s_b1[j0], s_b1[j0 + 1]);
            u64 acc[8];
#pragma unroll
            for (int nn = 0; nn < 8; nn++) acc[nn] = bias;
            const float* xp = s_h + nb * DD;
#pragma unroll 1
            for (int d4 = 0; d4 < DD; d4 += 4) {
                float4 xv[8];
#pragma unroll
                for (int nn = 0; nn < 8; nn++) xv[nn] = *(const float4*)&xp[nn * DD + d4];
#pragma unroll
                for (int dd = 0; dd < 4; dd++) {
                    u64 w = *(const u64*)&s_w1[(d4 + dd) * DA + j0];
#pragma unroll
                    for (int nn = 0; nn < 8; nn++)
                        acc[nn] = ffma2(w, dup2(((const float*)&xv[nn])[dd]), acc[nn]);
                }
            }
#pragma unroll
            for (int nn = 0; nn < 8; nn++) {
                float2 v = unpk(acc[nn]);
                *(float2*)&s_hid[(nb + nn) * HID + j0] =
                    make_float2(fmaxf(v.x, 0.f), fmaxf(v.y, 0.f));
            }
        }
        __syncwarp();

        if (act) {
            float4 bb = *(const float4*)&s_b2[k0];
            u64 a[8][2];
#pragma unroll
            for (int nn = 0; nn < 8; nn++) { a[nn][0] = pk2(bb.x, bb.y); a[nn][1] = pk2(bb.z, bb.w); }
            const float* hp = s_hid + nb * HID;
#pragma unroll 1
            for (int j4 = 0; j4 < HID; j4 += 4) {
                float4 hv[8];
#pragma unroll
                for (int nn = 0; nn < 8; nn++) hv[nn] = *(const float4*)&hp[nn * HID + j4];
#pragma unroll
                for (int dd = 0; dd < 4; dd++) {
                    ulonglong2 w = *(const ulonglong2*)&s_w2[(j4 + dd) * DD + k0];
#pragma unroll
                    for (int nn = 0; nn < 8; nn++) {
                        u64 v = dup2(((const float*)&hv[nn])[dd]);
                        a[nn][0] = ffma2(w.x, v, a[nn][0]);
                        a[nn][1] = ffma2(w.y, v, a[nn][1]);
                    }
                }
            }
#pragma unroll
            for (int nn = 0; nn < 8; nn++) {
                float2 p0 = unpk(a[nn][0]), p1 = unpk(a[nn][1]);
                *(float4*)&g_fm[(size_t)(base + nb + nn) * DD + k0] =
                    make_float4(p0.x, p0.y, p1.x, p1.y);
            }
        }
        __syncthreads();
        cur ^= 1;
    }
}

// ---------------- 6-pass GRU with FUSED CSR gather, 128-node tiles -------------------
// msg built in-prologue from g_fm via CSR (no gather kernel, no g_msg buffer).
// smem floats: wb0[5200] wb1[5200] xm[12800] xh[12800] bi[304] bh[304] = 36,608 -> 146,432 B
#define GRU_THREADS 512
#define GRU_NODES 128
#define GRU_SMEM_FLOATS 36608

__device__ __forceinline__ void prefetch_half(uint32_t dst, const float* __restrict__ srcWT,
                                              int ofs4, int d0, int rows, int tid) {
    int tot = rows * 25;
#pragma unroll 1
    for (int i = tid; i < tot; i += GRU_THREADS) {
        int d = d0 + i / 25, q = i - (i / 25) * 25;
        cpa16(dst + (uint32_t)i * 16u, (const void*)((const float4*)srcWT + d * 75 + ofs4 + q));
    }
}

__global__ void __launch_bounds__(GRU_THREADS, 1)
gru_kernel(const float* __restrict__ WTih, const float* __restrict__ WThh,
           const float* __restrict__ bih, const float* __restrict__ bhh,
           const int* __restrict__ rp, const int* __restrict__ deg,
           const int* __restrict__ eidx) {
    extern __shared__ float sm[];
    float* wb0  = sm;
    float* wb1  = sm + 5200;
    float* s_xm = sm + 10400;
    float* s_xh = sm + 23200;
    float* s_bi = sm + 36000;
    float* s_bh = sm + 36304;
    uint32_t waddr0 = smem_u32(wb0);
    uint32_t waddr1 = smem_u32(wb1);
    uint32_t xhaddr = smem_u32(s_xh);

    int tid = threadIdx.x;
    int base = blockIdx.x * GRU_NODES;
    int warp = tid >> 5, lane = tid & 31;
    int nb = warp * 8;
    int k0 = 4 * lane;
    bool act = lane < 25;

    const float* srcs[6] = {WTih, WThh, WThh, WTih, WTih, WThh};
    const int ofsv[6] = {0, 0, 50, 50, 25, 25};

    // ---- prologue: cp.async xh + weights; gather msg from g_fm via CSR (overlaps) ----
#pragma unroll 1
    for (int i = tid; i < 3200; i += GRU_THREADS)
        cpa16(xhaddr + (uint32_t)i * 16u, (const void*)(((const float4*)g_h) + base * 25 + i));
    prefetch_half(waddr0, WTih, 0, 0, 52, tid);
    CPA_COMMIT();
    prefetch_half(waddr1, WTih, 0, 52, 48, tid);
    CPA_COMMIT();
    for (int i = tid; i < TD; i += GRU_THREADS) { s_bi[i] = bih[i]; s_bh[i] = bhh[i]; }

    if (act) {
#pragma unroll 1
        for (int nn = 0; nn < 8; nn++) {
            int node = base + nb + nn;
            int s0 = __ldg(&rp[node]);
            int cnt = __ldg(&deg[node]);
            float4 a = make_float4(0.f, 0.f, 0.f, 0.f);
#pragma unroll 1
            for (int i = 0; i < cnt; i++) {
                int s = __ldg(&eidx[s0 + i]);
                float4 v = *(const float4*)&g_fm[(size_t)s * DD + k0];
                a.x += v.x; a.y += v.y; a.z += v.z; a.w += v.w;
            }
            *(float4*)&s_xm[(nb + nn) * DD + k0] = a;
        }
    }

    u64 acc[8][2];
    float rg[8][4];

#define MATVEC_H(SXBASE, CW, D0, ROWS) do { \
        const float* xp_ = (SXBASE) + nb * DD; \
        const float* cw_ = (CW); \
        _Pragma("unroll 1") \
        for (int d4 = 0; d4 < (ROWS); d4 += 4) { \
            float4 xv[8]; \
            _Pragma("unroll") \
            for (int nn = 0; nn < 8; nn++) xv[nn] = *(const float4*)&xp_[nn * DD + (D0) + d4]; \
            _Pragma("unroll") \
            for (int dd = 0; dd < 4; dd++) { \
                ulonglong2 w = *(const ulonglong2*)&cw_[(d4 + dd) * DD + k0]; \
                _Pragma("unroll") \
                for (int nn = 0; nn < 8; nn++) { \
                    u64 v = dup2(((const float*)&xv[nn])[dd]); \
                    acc[nn][0] = ffma2(w.x, v, acc[nn][0]); \
                    acc[nn][1] = ffma2(w.y, v, acc[nn][1]); \
                } \
            } \
        } \
    } while (0)

#define ZERO_ACC() do { \
        _Pragma("unroll") \
        for (int nn = 0; nn < 8; nn++) { acc[nn][0] = 0ULL; acc[nn][1] = 0ULL; } \
    } while (0)

#define HS_PRE() CPA_WAIT1(); __syncthreads()
#define HS_POST(GI) __syncthreads(); \
    { const int ni_ = (GI) + 2; \
      if (ni_ < 12) prefetch_half(((GI) & 1) ? waddr1 : waddr0, srcs[ni_ >> 1], ofsv[ni_ >> 1], \
                                  (ni_ & 1) ? 52 : 0, (ni_ & 1) ? 48 : 52, tid); } \
    CPA_COMMIT()

#define EPI_R() do { \
        float4 b1v = *(const float4*)&s_bi[k0]; \
        float4 b2v = *(const float4*)&s_bh[k0]; \
        _Pragma("unroll") \
        for (int nn = 0; nn < 8; nn++) { \
            float2 a0 = unpk(acc[nn][0]), a1 = unpk(acc[nn][1]); \
            rg[nn][0] = sigf(a0.x + b1v.x + b2v.x); \
            rg[nn][1] = sigf(a0.y + b1v.y + b2v.y); \
            rg[nn][2] = sigf(a1.x + b1v.z + b2v.z); \
            rg[nn][3] = sigf(a1.y + b1v.w + b2v.w); \
        } \
    } while (0)

#define EPI_N1() do { \
        float4 bn = *(const float4*)&s_bh[200 + k0]; \
        _Pragma("unroll") \
        for (int nn = 0; nn < 8; nn++) { \
            float2 a0 = unpk(acc[nn][0]), a1 = unpk(acc[nn][1]); \
            acc[nn][0] = pk2(rg[nn][0] * (a0.x + bn.x), rg[nn][1] * (a0.y + bn.y)); \
            acc[nn][1] = pk2(rg[nn][2] * (a1.x + bn.z), rg[nn][3] * (a1.y + bn.w)); \
        } \
    } while (0)

#define EPI_N2() do { \
        float4 bn = *(const float4*)&s_bi[200 + k0]; \
        _Pragma("unroll") \
        for (int nn = 0; nn < 8; nn++) { \
            float2 a0 = unpk(acc[nn][0]), a1 = unpk(acc[nn][1]); \
            rg[nn][0] = tanhf(a0.x + bn.x); \
            rg[nn][1] = tanhf(a0.y + bn.y); \
            rg[nn][2] = tanhf(a1.x + bn.z); \
            rg[nn][3] = tanhf(a1.y + bn.w); \
        } \
    } while (0)

#define EPI_Z() do { \
        float4 b1v = *(const float4*)&s_bi[100 + k0]; \
        float4 b2v = *(const float4*)&s_bh[100 + k0]; \
        _Pragma("unroll") \
        for (int nn = 0; nn < 8; nn++) { \
            float2 a0 = unpk(acc[nn][0]), a1 = unpk(acc[nn][1]); \
            float z0 = sigf(a0.x + b1v.x + b2v.x); \
            float z1 = sigf(a0.y + b1v.y + b2v.y); \
            float z2 = sigf(a1.x + b1v.z + b2v.z); \
            float z3 = sigf(a1.y + b1v.w + b2v.w); \
            float4 hv = *(const float4*)&s_xh[(nb + nn) * DD + k0]; \
            float4 o; \
            o.x = (1.f - z0) * rg[nn][0] + z0 * hv.x; \
            o.y = (1.f - z1) * rg[nn][1] + z1 * hv.y; \
            o.z = (1.f - z2) * rg[nn][2] + z2 * hv.z; \
            o.w = (1.f - z3) * rg[nn][3] + z3 * hv.w; \
            *(float4*)&g_h[(size_t)(base + nb + nn) * DD + k0] = o; \
        } \
    } while (0)

    HS_PRE(); if (act) { ZERO_ACC(); MATVEC_H(s_xm, wb0, 0, 52); } HS_POST(0);
    HS_PRE(); if (act) {             MATVEC_H(s_xm, wb1, 52, 48); } HS_POST(1);
    HS_PRE(); if (act) {             MATVEC_H(s_xh, wb0, 0, 52); } HS_POST(2);
    HS_PRE(); if (act) {             MATVEC_H(s_xh, wb1, 52, 48); EPI_R(); } HS_POST(3);
    HS_PRE(); if (act) { ZERO_ACC(); MATVEC_H(s_xh, wb0, 0, 52); } HS_POST(4);
    HS_PRE(); if (act) {             MATVEC_H(s_xh, wb1, 52, 48); EPI_N1(); } HS_POST(5);
    HS_PRE(); if (act) {             MATVEC_H(s_xm, wb0, 0, 52); } HS_POST(6);
    HS_PRE(); if (act) {             MATVEC_H(s_xm, wb1, 52, 48); EPI_N2(); } HS_POST(7);
    HS_PRE(); if (act) { ZERO_ACC(); MATVEC_H(s_xm, wb0, 0, 52); } HS_POST(8);
    HS_PRE(); if (act) {             MATVEC_H(s_xm, wb1, 52, 48); } HS_POST(9);
    HS_PRE(); if (act) {             MATVEC_H(s_xh, wb0, 0, 52); } HS_POST(10);
    HS_PRE(); if (act) {             MATVEC_H(s_xh, wb1, 52, 48); EPI_Z(); } HS_POST(11);

#undef MATVEC_H
#undef ZERO_ACC
#undef HS_PRE
#undef HS_POST
#undef EPI_R
#undef EPI_N1
#undef EPI_N2
#undef EPI_Z
}

// ---------------- classifier ----------------
__global__ void cls_kernel(const float* __restrict__ W1, const float* __restrict__ b1,
                           const float* __restrict__ W2, const float* __restrict__ b2,
                           float* __restrict__ out) {
    __shared__ float s_w1[DD * DC];
    __shared__ float s_b1[DC];
    __shared__ float s_w2[DC];
    __shared__ float s_row[8 * DD];

    int tid = threadIdx.x;
    int warp = tid >> 5, lane = tid & 31;
    int node = blockIdx.x * 8 + warp;

    for (int i = tid; i < DD * DC; i += blockDim.x) s_w1[i] = W1[i];
    if (tid < DC) { s_b1[tid] = b1[tid]; s_w2[tid] = W2[tid]; }
    __syncthreads();

    const float* hrow = &g_h[(size_t)node * DD];
    float* rbuf = &s_row[warp * DD];
    rbuf[lane] = hrow[lane];
    rbuf[lane + 32] = hrow[lane + 32];
    rbuf[lane + 64] = hrow[lane + 64];
    if (lane < 4) rbuf[lane + 96] = hrow[lane + 96];
    __syncwarp();

    float v = 0.f;
    if (lane < DC) {
        float acc = s_b1[lane];
#pragma unroll 4
        for (int d = 0; d < DD; d++) acc += rbuf[d] * s_w1[d * DC + lane];
        v = fmaxf(acc, 0.f) * s_w2[lane];
    }
#pragma unroll
    for (int off = 16; off > 0; off >>= 1) v += __shfl_down_sync(0xFFFFFFFFu, v, off);
    if (lane == 0) out[node] = v + b2[0];
}

// ---------------- host launch ----------------
extern "C" void kernel_launch(void* const* d_in, const int* in_sizes, int n_in,
                              void* d_out, int out_size) {
    const float* features = (const float*)d_in[0];
    const int* edge_row   = (const int*)d_in[1];
    const int* edge_col   = (const int*)d_in[2];
    const float* init_W = (const float*)d_in[3];
    const float* init_b = (const float*)d_in[4];
    const float* fmsg_W1 = (const float*)d_in[5];
    const float* fmsg_b1 = (const float*)d_in[6];
    const float* fmsg_W2 = (const float*)d_in[7];
    const float* fmsg_b2 = (const float*)d_in[8];
    const float* bmsg_W1 = (const float*)d_in[9];
    const float* bmsg_b1 = (const float*)d_in[10];
    const float* bmsg_W2 = (const float*)d_in[11];
    const float* bmsg_b2 = (const float*)d_in[12];
    const float* fgru_Wih = (const float*)d_in[13];
    const float* fgru_Whh = (const float*)d_in[14];
    const float* fgru_bih = (const float*)d_in[15];
    const float* fgru_bhh = (const float*)d_in[16];
    const float* bgru_Wih = (const float*)d_in[17];
    const float* bgru_Whh = (const float*)d_in[18];
    const float* bgru_bih = (const float*)d_in[19];
    const float* bgru_bhh = (const float*)d_in[20];
    const float* cls_W1 = (const float*)d_in[21];
    const float* cls_b1 = (const float*)d_in[22];
    const float* cls_W2 = (const float*)d_in[23];
    const float* cls_b2 = (const float*)d_in[24];
    float* out = (float*)d_out;

    const int mlp_smem = MLP_SMEM_FLOATS * 4;   // 105,968 B
    const int gru_smem = GRU_SMEM_FLOATS * 4;   // 146,432 B
    cudaFuncSetAttribute((const void*)mlp_kernel,
                         cudaFuncAttributeMaxDynamicSharedMemorySize, mlp_smem);
    cudaFuncSetAttribute((const void*)gru_kernel,
                         cudaFuncAttributeMaxDynamicSharedMemorySize, gru_smem);

    // resolve device-global scratch addresses
    float* wt_base = nullptr;
    cudaGetSymbolAddress((void**)&wt_base, g_WT);
    const float* fWihT = wt_base;
    const float* fWhhT = wt_base + 30000;
    const float* bWihT = wt_base + 60000;
    const float* bWhhT = wt_base + 90000;
    int *rpF, *rpB, *degF, *degB, *eF, *eB;
    cudaGetSymbolAddress((void**)&rpF, g_rpF);
    cudaGetSymbolAddress((void**)&rpB, g_rpB);
    cudaGetSymbolAddress((void**)&degF, g_degF);
    cudaGetSymbolAddress((void**)&degB, g_degB);
    cudaGetSymbolAddress((void**)&eF, g_eF);
    cudaGetSymbolAddress((void**)&eB, g_eB);

    init_kernel<<<(ND + 255) / 256, 256>>>(features, init_W, init_b);
    transpose_w_kernel<<<(30000 + 255) / 256, 256>>>(fgru_Wih, fgru_Whh, bgru_Wih, bgru_Whh);

    // CSR build (edges constant across rounds)
    zero_deg_kernel<<<NN / 256, 256>>>();
    count_deg_kernel<<<EE / 256, 256>>>(edge_row, edge_col);
    scan1_kernel<<<256, 256>>>();
    scan2_kernel<<<1, 2>>>();
    scan3_kernel<<<(2 * NN) / 256, 256>>>();
    fill_csr_kernel<<<EE / 256, 256>>>(edge_row, edge_col);

    const int gru_blocks = NN / GRU_NODES;   // 1024

    for (int r = 0; r < 20; r++) {
        // forward: msg[row] = sum fm[col]  (gather fused into GRU)
        mlp_kernel<<<PGRID, MLP_THREADS, mlp_smem>>>(fmsg_W1, fmsg_b1, fmsg_W2, fmsg_b2);
        gru_kernel<<<gru_blocks, GRU_THREADS, gru_smem>>>(fWihT, fWhhT, fgru_bih, fgru_bhh,
                                                          rpF, degF, eF);
        // backward: msg[col] = sum bm[row]
        mlp_kernel<<<PGRID, MLP_THREADS, mlp_smem>>>(bmsg_W1, bmsg_b1, bmsg_W2, bmsg_b2);
        gru_kernel<<<gru_blocks, GRU_THREADS, gru_smem>>>(bWihT, bWhhT, bgru_bih, bgru_bhh,
                                                          rpB, degB, eB);
    }

    cls_kernel<<<NN / 8, 256>>>(cls_W1, cls_b1, cls_W2, cls_b2, out);
    (void)in_sizes; (void)n_in; (void)out_size;
}

// round 15
// speedup vs baseline: 1.0768x; 1.0768x over previous
#include <cuda_runtime.h>
#include <cuda_bf16.h>
#include <cstdint>

// ---------------- problem constants ----------------
#define NN 131072
#define EE 524288
#define DD 100
#define TD 300
#define DA 50
#define DC 30
#define ND (NN*DD)          // 13,107,200
#define PGRID 304           // persistent grid (2 CTAs/SM on 152-SM GB300)

// ---------------- scratch (static device globals; no allocation) ----------------
__device__ float g_h[ND];
__device__ float g_fm[ND];
__device__ float g_msg[ND];
__device__ float g_WT[4][30000];   // pre-transposed [d][j] GRU weights: fWih,fWhh,bWih,bWhh

// CSR scratch (edges constant -> build once per launch)
__device__ int g_degF[NN], g_degB[NN];
__device__ int g_rpF[NN], g_rpB[NN];
__device__ int g_fillF[NN], g_fillB[NN];
__device__ int g_eF[EE], g_eB[EE];
__device__ int g_bsum[256];

// ---------------- f32x2 packed-FMA helpers (sm_103a FFMA2 path) ----------------
typedef unsigned long long u64;

__device__ __forceinline__ u64 ffma2(u64 a, u64 b, u64 c) {
    u64 d;
    asm("fma.rn.f32x2 %0, %1, %2, %3;" : "=l"(d) : "l"(a), "l"(b), "l"(c));
    return d;
}
__device__ __forceinline__ u64 dup2(float x) {
    u64 d;
    asm("mov.b64 %0, {%1, %1};" : "=l"(d) : "f"(x));
    return d;
}
__device__ __forceinline__ u64 pk2(float a, float b) {
    u64 d;
    asm("mov.b64 %0, {%1, %2};" : "=l"(d) : "f"(a), "f"(b));
    return d;
}
__device__ __forceinline__ float2 unpk(u64 a) {
    float2 r;
    asm("mov.b64 {%0, %1}, %2;" : "=f"(r.x), "=f"(r.y) : "l"(a));
    return r;
}
__device__ __forceinline__ float sigf(float v) {
    return 1.0f / (1.0f + __expf(-v));
}
__device__ __forceinline__ uint32_t smem_u32(const void* p) {
    uint32_t a;
    asm("{ .reg .u64 t; cvta.to.shared.u64 t, %1; cvt.u32.u64 %0, t; }" : "=r"(a) : "l"(p));
    return a;
}
__device__ __forceinline__ void cpa16(uint32_t saddr, const void* g) {
    asm volatile("cp.async.cg.shared.global [%0], [%1], 16;" :: "r"(saddr), "l"(g));
}
#define CPA_COMMIT() asm volatile("cp.async.commit_group;" ::: "memory")
#define CPA_WAIT1()  asm volatile("cp.async.wait_group 1;" ::: "memory")

// ---------------- init: h = features @ init_W + init_b ----------------
__global__ void init_kernel(const float* __restrict__ feat,
                            const float* __restrict__ W,
                            const float* __restrict__ b) {
    int i = blockIdx.x * blockDim.x + threadIdx.x;
    if (i >= ND) return;
    int n = i / DD;
    int d = i - n * DD;
    float f0 = feat[n * 4 + 0], f1 = feat[n * 4 + 1];
    float f2 = feat[n * 4 + 2], f3 = feat[n * 4 + 3];
    g_h[i] = b[d] + f0 * W[d] + f1 * W[DD + d] + f2 * W[2 * DD + d] + f3 * W[3 * DD + d];
}

// ---------------- one-time weight transpose: g_WT[m][d*300+j] = W[j*100+d] ----------------
__global__ void transpose_w_kernel(const float* __restrict__ A, const float* __restrict__ B,
                                   const float* __restrict__ C, const float* __restrict__ E) {
    int i = blockIdx.x * blockDim.x + threadIdx.x;
    if (i >= 30000) return;
    int d = i / TD, j = i - d * TD;
    int src = j * DD + d;
    g_WT[0][i] = A[src];
    g_WT[1][i] = B[src];
    g_WT[2][i] = C[src];
    g_WT[3][i] = E[src];
}

// ---------------- CSR build kernels ----------------
__global__ void zero_deg_kernel() {
    int i = blockIdx.x * blockDim.x + threadIdx.x;
    g_degF[i] = 0;
    g_degB[i] = 0;
}
__global__ void count_deg_kernel(const int* __restrict__ row, const int* __restrict__ col) {
    int e = blockIdx.x * blockDim.x + threadIdx.x;
    atomicAdd(&g_degF[row[e]], 1);
    atomicAdd(&g_degB[col[e]], 1);
}
__global__ void scan1_kernel() {
    __shared__ int s[1024];
    int b = blockIdx.x;
    const int* deg = (b < 128) ? g_degF : g_degB;
    int* rp = (b < 128) ? g_rpF : g_rpB;
    int base = (b & 127) * 1024;
    for (int i = threadIdx.x; i < 1024; i += blockDim.x) s[i] = deg[base + i];
    __syncthreads();
    if (threadIdx.x == 0) {
        int run = 0;
        for (int i = 0; i < 1024; i++) { int v = s[i]; s[i] = run; run += v; }
        g_bsum[b] = run;
    }
    __syncthreads();
    for (int i = threadIdx.x; i < 1024; i += blockDim.x) rp[base + i] = s[i];
}
__global__ void scan2_kernel() {
    int t = threadIdx.x;
    int base = t * 128;
    int run = 0;
    for (int i = 0; i < 128; i++) { int v = g_bsum[base + i]; g_bsum[base + i] = run; run += v; }
}
__global__ void scan3_kernel() {
    int i = blockIdx.x * blockDim.x + threadIdx.x;
    if (i < NN) {
        int v = g_rpF[i] + g_bsum[i >> 10];
        g_rpF[i] = v; g_fillF[i] = v;
    } else {
        int j = i - NN;
        int v = g_rpB[j] + g_bsum[128 + (j >> 10)];
        g_rpB[j] = v; g_fillB[j] = v;
    }
}
__global__ void fill_csr_kernel(const int* __restrict__ row, const int* __restrict__ col) {
    int e = blockIdx.x * blockDim.x + threadIdx.x;
    int r = row[e], c = col[e];
    int pF = atomicAdd(&g_fillF[r], 1);
    g_eF[pF] = c;
    int pB = atomicAdd(&g_fillB[c], 1);
    g_eB[pB] = r;
}

// ---------------- gather with 4-edge ILP: msg[n] = sum fm[eidx[e]] ----------------
__global__ void gather_kernel(const int* __restrict__ rp, const int* __restrict__ deg,
                              const int* __restrict__ eidx) {
    int node = (blockIdx.x * blockDim.x + threadIdx.x) >> 5;
    int lane = threadIdx.x & 31;
    if (lane >= 25) return;
    int s0 = rp[node];
    int cnt = deg[node];
    int k0 = 4 * lane;
    float4 acc = make_float4(0.f, 0.f, 0.f, 0.f);
    int i = 0;
#pragma unroll 1
    for (; i + 4 <= cnt; i += 4) {
        int sa = __ldg(&eidx[s0 + i]);
        int sb = __ldg(&eidx[s0 + i + 1]);
        int sc = __ldg(&eidx[s0 + i + 2]);
        int sd = __ldg(&eidx[s0 + i + 3]);
        float4 v0 = *(const float4*)&g_fm[(size_t)sa * DD + k0];
        float4 v1 = *(const float4*)&g_fm[(size_t)sb * DD + k0];
        float4 v2 = *(const float4*)&g_fm[(size_t)sc * DD + k0];
        float4 v3 = *(const float4*)&g_fm[(size_t)sd * DD + k0];
        acc.x += (v0.x + v1.x) + (v2.x + v3.x);
        acc.y += (v0.y + v1.y) + (v2.y + v3.y);
        acc.z += (v0.z + v1.z) + (v2.z + v3.z);
        acc.w += (v0.w + v1.w) + (v2.w + v3.w);
    }
#pragma unroll 1
    for (; i < cnt; i++) {
        int s = __ldg(&eidx[s0 + i]);
        float4 v = *(const float4*)&g_fm[(size_t)s * DD + k0];
        acc.x += v.x; acc.y += v.y; acc.z += v.z; acc.w += v.w;
    }
    *(float4*)&g_msg[(size_t)node * DD + k0] = acc;
}

// ---------------- persistent MLP (R10 passing form) ----------------
#define MLP_THREADS 256
#define MLP_NODES 64
#define HID 52
#define MLP_SMEM_FLOATS 26492

__global__ void __launch_bounds__(MLP_THREADS, 2)
mlp_kernel(const float* __restrict__ W1, const float* __restrict__ b1,
           const float* __restrict__ W2, const float* __restrict__ b2) {
    extern __shared__ float smem[];
    float* s_w1 = smem;
    float* s_w2 = smem + 5000;
    float* s_hid = smem + 10200;
    float* s_b2 = smem + 13528;
    float* s_b1 = smem + 13628;
    float* xb[2] = {smem + 13692, smem + 20092};
    uint32_t xaddr[2] = {smem_u32(xb[0]), smem_u32(xb[1])};

    int tid = threadIdx.x;
    int warp = tid >> 5, lane = tid & 31;
    int nb = warp * 8;
    int k0 = 4 * lane;
    bool act = lane < 25;
    const int NTILES = NN / MLP_NODES;   // 2048

#pragma unroll 1
    for (int i = tid; i < 1600; i += MLP_THREADS)
        cpa16(xaddr[0] + (uint32_t)i * 16u,
              (const void*)(((const float4*)g_h) + (size_t)blockIdx.x * 1600 + i));
    CPA_COMMIT();

    for (int i = tid; i < 5000; i += MLP_THREADS) s_w1[i] = W1[i];
    for (int i = tid; i < HID * DD; i += MLP_THREADS) s_w2[i] = (i < 5000) ? W2[i] : 0.f;
    if (tid < DD) s_b2[tid] = b2[tid];
    if (tid < DA) s_b1[tid] = b1[tid];
    if (lane == 25) {
#pragma unroll
        for (int nn = 0; nn < 8; nn++)
            *(float2*)&s_hid[(nb + nn) * HID + 50] = make_float2(0.f, 0.f);
    }

    int cur = 0;
#pragma unroll 1
    for (int tile = blockIdx.x; tile < NTILES; tile += PGRID) {
        int ntile = tile + PGRID;
        if (ntile < NTILES) {
#pragma unroll 1
            for (int i = tid; i < 1600; i += MLP_THREADS)
                cpa16(xaddr[cur ^ 1] + (uint32_t)i * 16u,
                      (const void*)(((const float4*)g_h) + (size_t)ntile * 1600 + i));
        }
        CPA_COMMIT();
        CPA_WAIT1();
        __syncthreads();

        int base = tile * MLP_NODES;
        const float* s_h = xb[cur];

        if (act) {
            int j0 = 2 * lane;
            u64 bias = pk2(s_b1[j0], s_b1[j0 + 1]);
            u64 acc[8];
#pragma unroll
            for (int nn = 0; nn < 8; nn++) acc[nn] = bias;
            const float* xp = s_h + nb * DD;
#pragma unroll 1
            for (int d4 = 0; d4 < DD; d4 += 4) {
                float4 xv[8];
#pragma unroll
                for (int nn = 0; nn < 8; nn++) xv[nn] = *(const float4*)&xp[nn * DD + d4];
#pragma unroll
                for (int dd = 0; dd < 4; dd++) {
                    u64 w = *(const u64*)&s_w1[(d4 + dd) * DA + j0];
#pragma unroll
                    for (int nn = 0; nn < 8; nn++)
                        acc[nn] = ffma2(w, dup2(((const float*)&xv[nn])[dd]), acc[nn]);
                }
            }
#pragma unroll
            for (int nn = 0; nn < 8; nn++) {
                float2 v = unpk(acc[nn]);
                *(float2*)&s_hid[(nb + nn) * HID + j0] =
                    make_float2(fmaxf(v.x, 0.f), fmaxf(v.y, 0.f));
            }
        }
        __syncwarp();

        if (act) {
            float4 bb = *(const float4*)&s_b2[k0];
            u64 a[8][2];
#pragma unroll
            for (int nn = 0; nn < 8; nn++) { a[nn][0] = pk2(bb.x, bb.y); a[nn][1] = pk2(bb.z, bb.w); }
            const float* hp = s_hid + nb * HID;
#pragma unroll 1
            for (int j4 = 0; j4 < HID; j4 += 4) {
                float4 hv[8];
#pragma unroll
                for (int nn = 0; nn < 8; nn++) hv[nn] = *(const float4*)&hp[nn * HID + j4];
#pragma unroll
                for (int dd = 0; dd < 4; dd++) {
                    ulonglong2 w = *(const ulonglong2*)&s_w2[(j4 + dd) * DD + k0];
#pragma unroll
                    for (int nn = 0; nn < 8; nn++) {
                        u64 v = dup2(((const float*)&hv[nn])[dd]);
                        a[nn][0] = ffma2(w.x, v, a[nn][0]);
                        a[nn][1] = ffma2(w.y, v, a[nn][1]);
                    }
                }
            }
#pragma unroll
            for (int nn = 0; nn < 8; nn++) {
                float2 p0 = unpk(a[nn][0]), p1 = unpk(a[nn][1]);
                *(float4*)&g_fm[(size_t)(base + nb + nn) * DD + k0] =
                    make_float4(p0.x, p0.y, p1.x, p1.y);
            }
        }
        __syncthreads();
        cur ^= 1;
    }
}

// ---------------- 6-pass GRU, 128-node tiles (512 thr), cp.async weight pipeline ----------
// smem floats: wb0[5200] wb1[5200] xm[12800] xh[12800] bi[304] bh[304] = 36,608 -> 146,432 B
#define GRU_THREADS 512
#define GRU_NODES 128
#define GRU_SMEM_FLOATS 36608

__device__ __forceinline__ void prefetch_half(uint32_t dst, const float* __restrict__ srcWT,
                                              int ofs4, int d0, int rows, int tid) {
    int tot = rows * 25;
#pragma unroll 1
    for (int i = tid; i < tot; i += GRU_THREADS) {
        int d = d0 + i / 25, q = i - (i / 25) * 25;
        cpa16(dst + (uint32_t)i * 16u, (const void*)((const float4*)srcWT + d * 75 + ofs4 + q));
    }
}

__global__ void __launch_bounds__(GRU_THREADS, 1)
gru_kernel(const float* __restrict__ WTih, const float* __restrict__ WThh,
           const float* __restrict__ bih, const float* __restrict__ bhh) {
    extern __shared__ float sm[];
    float* wb0  = sm;
    float* wb1  = sm + 5200;
    float* s_xm = sm + 10400;
    float* s_xh = sm + 23200;
    float* s_bi = sm + 36000;
    float* s_bh = sm + 36304;
    uint32_t waddr0 = smem_u32(wb0);
    uint32_t waddr1 = smem_u32(wb1);
    uint32_t xmaddr = smem_u32(s_xm);
    uint32_t xhaddr = smem_u32(s_xh);

    int tid = threadIdx.x;
    int base = blockIdx.x * GRU_NODES;
    int warp = tid >> 5, lane = tid & 31;
    int nb = warp * 8;
    int k0 = 4 * lane;
    bool act = lane < 25;

    const float* srcs[6] = {WTih, WThh, WThh, WTih, WTih, WThh};
    const int ofsv[6] = {0, 0, 50, 50, 25, 25};

#pragma unroll 1
    for (int i = tid; i < 3200; i += GRU_THREADS) {
        cpa16(xmaddr + (uint32_t)i * 16u, (const void*)(((const float4*)g_msg) + base * 25 + i));
        cpa16(xhaddr + (uint32_t)i * 16u, (const void*)(((const float4*)g_h)   + base * 25 + i));
    }
    prefetch_half(waddr0, WTih, 0, 0, 52, tid);
    CPA_COMMIT();
    prefetch_half(waddr1, WTih, 0, 52, 48, tid);
    CPA_COMMIT();
    for (int i = tid; i < TD; i += GRU_THREADS) { s_bi[i] = bih[i]; s_bh[i] = bhh[i]; }

    u64 acc[8][2];
    float rg[8][4];

#define MATVEC_H(SXBASE, CW, D0, ROWS) do { \
        const float* xp_ = (SXBASE) + nb * DD; \
        const float* cw_ = (CW); \
        _Pragma("unroll 1") \
        for (int d4 = 0; d4 < (ROWS); d4 += 4) { \
            float4 xv[8]; \
            _Pragma("unroll") \
            for (int nn = 0; nn < 8; nn++) xv[nn] = *(const float4*)&xp_[nn * DD + (D0) + d4]; \
            _Pragma("unroll") \
            for (int dd = 0; dd < 4; dd++) { \
                ulonglong2 w = *(const ulonglong2*)&cw_[(d4 + dd) * DD + k0]; \
                _Pragma("unroll") \
                for (int nn = 0; nn < 8; nn++) { \
                    u64 v = dup2(((const float*)&xv[nn])[dd]); \
                    acc[nn][0] = ffma2(w.x, v, acc[nn][0]); \
                    acc[nn][1] = ffma2(w.y, v, acc[nn][1]); \
                } \
            } \
        } \
    } while (0)

#define ZERO_ACC() do { \
        _Pragma("unroll") \
        for (int nn = 0; nn < 8; nn++) { acc[nn][0] = 0ULL; acc[nn][1] = 0ULL; } \
    } while (0)

#define HS_PRE() CPA_WAIT1(); __syncthreads()
#define HS_POST(GI) __syncthreads(); \
    { const int ni_ = (GI) + 2; \
      if (ni_ < 12) prefetch_half(((GI) & 1) ? waddr1 : waddr0, srcs[ni_ >> 1], ofsv[ni_ >> 1], \
                                  (ni_ & 1) ? 52 : 0, (ni_ & 1) ? 48 : 52, tid); } \
    CPA_COMMIT()

#define EPI_R() do { \
        float4 b1v = *(const float4*)&s_bi[k0]; \
        float4 b2v = *(const float4*)&s_bh[k0]; \
        _Pragma("unroll") \
        for (int nn = 0; nn < 8; nn++) { \
            float2 a0 = unpk(acc[nn][0]), a1 = unpk(acc[nn][1]); \
            rg[nn][0] = sigf(a0.x + b1v.x + b2v.x); \
            rg[nn][1] = sigf(a0.y + b1v.y + b2v.y); \
            rg[nn][2] = sigf(a1.x + b1v.z + b2v.z); \
            rg[nn][3] = sigf(a1.y + b1v.w + b2v.w); \
        } \
    } while (0)

#define EPI_N1() do { \
        float4 bn = *(const float4*)&s_bh[200 + k0]; \
        _Pragma("unroll") \
        for (int nn = 0; nn < 8; nn++) { \
            float2 a0 = unpk(acc[nn][0]), a1 = unpk(acc[nn][1]); \
            acc[nn][0] = pk2(rg[nn][0] * (a0.x + bn.x), rg[nn][1] * (a0.y + bn.y)); \
            acc[nn][1] = pk2(rg[nn][2] * (a1.x + bn.z), rg[nn][3] * (a1.y + bn.w)); \
        } \
    } while (0)

#define EPI_N2() do { \
        float4 bn = *(const float4*)&s_bi[200 + k0]; \
        _Pragma("unroll") \
        for (int nn = 0; nn < 8; nn++) { \
            float2 a0 = unpk(acc[nn][0]), a1 = unpk(acc[nn][1]); \
            rg[nn][0] = tanhf(a0.x + bn.x); \
            rg[nn][1] = tanhf(a0.y + bn.y); \
            rg[nn][2] = tanhf(a1.x + bn.z); \
            rg[nn][3] = tanhf(a1.y + bn.w); \
        } \
    } while (0)

#define EPI_Z() do { \
        float4 b1v = *(const float4*)&s_bi[100 + k0]; \
        float4 b2v = *(const float4*)&s_bh[100 + k0]; \
        _Pragma("unroll") \
        for (int nn = 0; nn < 8; nn++) { \
            float2 a0 = unpk(acc[nn][0]), a1 = unpk(acc[nn][1]); \
            float z0 = sigf(a0.x + b1v.x + b2v.x); \
            float z1 = sigf(a0.y + b1v.y + b2v.y); \
            float z2 = sigf(a1.x + b1v.z + b2v.z); \
            float z3 = sigf(a1.y + b1v.w + b2v.w); \
            float4 hv = *(const float4*)&s_xh[(nb + nn) * DD + k0]; \
            float4 o; \
            o.x = (1.f - z0) * rg[nn][0] + z0 * hv.x; \
            o.y = (1.f - z1) * rg[nn][1] + z1 * hv.y; \
            o.z = (1.f - z2) * rg[nn][2] + z2 * hv.z; \
            o.w = (1.f - z3) * rg[nn][3] + z3 * hv.w; \
            *(float4*)&g_h[(size_t)(base + nb + nn) * DD + k0] = o; \
        } \
    } while (0)

    HS_PRE(); if (act) { ZERO_ACC(); MATVEC_H(s_xm, wb0, 0, 52); } HS_POST(0);
    HS_PRE(); if (act) {             MATVEC_H(s_xm, wb1, 52, 48); } HS_POST(1);
    HS_PRE(); if (act) {             MATVEC_H(s_xh, wb0, 0, 52); } HS_POST(2);
    HS_PRE(); if (act) {             MATVEC_H(s_xh, wb1, 52, 48); EPI_R(); } HS_POST(3);
    HS_PRE(); if (act) { ZERO_ACC(); MATVEC_H(s_xh, wb0, 0, 52); } HS_POST(4);
    HS_PRE(); if (act) {             MATVEC_H(s_xh, wb1, 52, 48); EPI_N1(); } HS_POST(5);
    HS_PRE(); if (act) {             MATVEC_H(s_xm, wb0, 0, 52); } HS_POST(6);
    HS_PRE(); if (act) {             MATVEC_H(s_xm, wb1, 52, 48); EPI_N2(); } HS_POST(7);
    HS_PRE(); if (act) { ZERO_ACC(); MATVEC_H(s_xm, wb0, 0, 52); } HS_POST(8);
    HS_PRE(); if (act) {             MATVEC_H(s_xm, wb1, 52, 48); } HS_POST(9);
    HS_PRE(); if (act) {             MATVEC_H(s_xh, wb0, 0, 52); } HS_POST(10);
    HS_PRE(); if (act) {             MATVEC_H(s_xh, wb1, 52, 48); EPI_Z(); } HS_POST(11);

#undef MATVEC_H
#undef ZERO_ACC
#undef HS_PRE
#undef HS_POST
#undef EPI_R
#undef EPI_N1
#undef EPI_N2
#undef EPI_Z
}

// ---------------- classifier ----------------
__global__ void cls_kernel(const float* __restrict__ W1, const float* __restrict__ b1,
                           const float* __restrict__ W2, const float* __restrict__ b2,
                           float* __restrict__ out) {
    __shared__ float s_w1[DD * DC];
    __shared__ float s_b1[DC];
    __shared__ float s_w2[DC];
    __shared__ float s_row[8 * DD];

    int tid = threadIdx.x;
    int warp = tid >> 5, lane = tid & 31;
    int node = blockIdx.x * 8 + warp;

    for (int i = tid; i < DD * DC; i += blockDim.x) s_w1[i] = W1[i];
    if (tid < DC) { s_b1[tid] = b1[tid]; s_w2[tid] = W2[tid]; }
    __syncthreads();

    const float* hrow = &g_h[(size_t)node * DD];
    float* rbuf = &s_row[warp * DD];
    rbuf[lane] = hrow[lane];
    rbuf[lane + 32] = hrow[lane + 32];
    rbuf[lane + 64] = hrow[lane + 64];
    if (lane < 4) rbuf[lane + 96] = hrow[lane + 96];
    __syncwarp();

    float v = 0.f;
    if (lane < DC) {
        float acc = s_b1[lane];
#pragma unroll 4
        for (int d = 0; d < DD; d++) acc += rbuf[d] * s_w1[d * DC + lane];
        v = fmaxf(acc, 0.f) * s_w2[lane];
    }
#pragma unroll
    for (int off = 16; off > 0; off >>= 1) v += __shfl_down_sync(0xFFFFFFFFu, v, off);
    if (lane == 0) out[node] = v + b2[0];
}

// ---------------- host launch ----------------
extern "C" void kernel_launch(void* const* d_in, const int* in_sizes, int n_in,
                              void* d_out, int out_size) {
    const float* features = (const float*)d_in[0];
    const int* edge_row   = (const int*)d_in[1];
    const int* edge_col   = (const int*)d_in[2];
    const float* init_W = (const float*)d_in[3];
    const float* init_b = (const float*)d_in[4];
    const float* fmsg_W1 = (const float*)d_in[5];
    const float* fmsg_b1 = (const float*)d_in[6];
    const float* fmsg_W2 = (const float*)d_in[7];
    const float* fmsg_b2 = (const float*)d_in[8];
    const float* bmsg_W1 = (const float*)d_in[9];
    const float* bmsg_b1 = (const float*)d_in[10];
    const float* bmsg_W2 = (const float*)d_in[11];
    const float* bmsg_b2 = (const float*)d_in[12];
    const float* fgru_Wih = (const float*)d_in[13];
    const float* fgru_Whh = (const float*)d_in[14];
    const float* fgru_bih = (const float*)d_in[15];
    const float* fgru_bhh = (const float*)d_in[16];
    const float* bgru_Wih = (const float*)d_in[17];
    const float* bgru_Whh = (const float*)d_in[18];
    const float* bgru_bih = (const float*)d_in[19];
    const float* bgru_bhh = (const float*)d_in[20];
    const float* cls_W1 = (const float*)d_in[21];
    const float* cls_b1 = (const float*)d_in[22];
    const float* cls_W2 = (const float*)d_in[23];
    const float* cls_b2 = (const float*)d_in[24];
    float* out = (float*)d_out;

    const int mlp_smem = MLP_SMEM_FLOATS * 4;   // 105,968 B
    const int gru_smem = GRU_SMEM_FLOATS * 4;   // 146,432 B
    cudaFuncSetAttribute((const void*)mlp_kernel,
                         cudaFuncAttributeMaxDynamicSharedMemorySize, mlp_smem);
    cudaFuncSetAttribute((const void*)gru_kernel,
                         cudaFuncAttributeMaxDynamicSharedMemorySize, gru_smem);

    // resolve device-global scratch addresses
    float* wt_base = nullptr;
    cudaGetSymbolAddress((void**)&wt_base, g_WT);
    const float* fWihT = wt_base;
    const float* fWhhT = wt_base + 30000;
    const float* bWihT = wt_base + 60000;
    const float* bWhhT = wt_base + 90000;
    int *rpF, *rpB, *degF, *degB, *eF, *eB;
    cudaGetSymbolAddress((void**)&rpF, g_rpF);
    cudaGetSymbolAddress((void**)&rpB, g_rpB);
    cudaGetSymbolAddress((void**)&degF, g_degF);
    cudaGetSymbolAddress((void**)&degB, g_degB);
    cudaGetSymbolAddress((void**)&eF, g_eF);
    cudaGetSymbolAddress((void**)&eB, g_eB);

    init_kernel<<<(ND + 255) / 256, 256>>>(features, init_W, init_b);
    transpose_w_kernel<<<(30000 + 255) / 256, 256>>>(fgru_Wih, fgru_Whh, bgru_Wih, bgru_Whh);

    // CSR build (edges constant across rounds)
    zero_deg_kernel<<<NN / 256, 256>>>();
    count_deg_kernel<<<EE / 256, 256>>>(edge_row, edge_col);
    scan1_kernel<<<256, 256>>>();
    scan2_kernel<<<1, 2>>>();
    scan3_kernel<<<(2 * NN) / 256, 256>>>();
    fill_csr_kernel<<<EE / 256, 256>>>(edge_row, edge_col);

    const int gru_blocks = NN / GRU_NODES;   // 1024
    const int gat_blocks = NN / 8;           // 16384

    for (int r = 0; r < 20; r++) {
        // forward: msg[row] = sum fm[col]
        mlp_kernel<<<PGRID, MLP_THREADS, mlp_smem>>>(fmsg_W1, fmsg_b1, fmsg_W2, fmsg_b2);
        gather_kernel<<<gat_blocks, 256>>>(rpF, degF, eF);
        gru_kernel<<<gru_blocks, GRU_THREADS, gru_smem>>>(fWihT, fWhhT, fgru_bih, fgru_bhh);
        // backward: msg[col] = sum bm[row]
        mlp_kernel<<<PGRID, MLP_THREADS, mlp_smem>>>(bmsg_W1, bmsg_b1, bmsg_W2, bmsg_b2);
        gather_kernel<<<gat_blocks, 256>>>(rpB, degB, eB);
        gru_kernel<<<gru_blocks, GRU_THREADS, gru_smem>>>(bWihT, bWhhT, bgru_bih, bgru_bhh);
    }

    cls_kernel<<<NN / 8, 256>>>(cls_W1, cls_b1, cls_W2, cls_b2, out);
    (void)in_sizes; (void)n_in; (void)out_size;
}

// round 16
// speedup vs baseline: 1.1087x; 1.0296x over previous
#include <cuda_runtime.h>
#include <cuda_bf16.h>
#include <cstdint>

// ---------------- problem constants ----------------
#define NN 131072
#define EE 524288
#define DD 100
#define TD 300
#define DA 50
#define DC 30
#define ND (NN*DD)          // 13,107,200
#define PGRID 304           // persistent grid (2 CTAs/SM on 152-SM GB300)

// ---------------- scratch (static device globals; no allocation) ----------------
__device__ float g_h[ND];
__device__ float g_fm[ND];
__device__ float g_msg[ND];
__device__ float g_WT[4][30000];   // pre-transposed [d][j] GRU weights: fWih,fWhh,bWih,bWhh

// CSR scratch (edges constant -> build once per launch)
__device__ int g_degF[NN], g_degB[NN];
__device__ int g_rpF[NN], g_rpB[NN];
__device__ int g_fillF[NN], g_fillB[NN];
__device__ int g_eF[EE], g_eB[EE];
__device__ int g_bsum[256];

// ---------------- f32x2 packed-FMA helpers (sm_103a FFMA2 path) ----------------
typedef unsigned long long u64;

__device__ __forceinline__ u64 ffma2(u64 a, u64 b, u64 c) {
    u64 d;
    asm("fma.rn.f32x2 %0, %1, %2, %3;" : "=l"(d) : "l"(a), "l"(b), "l"(c));
    return d;
}
__device__ __forceinline__ u64 dup2(float x) {
    u64 d;
    asm("mov.b64 %0, {%1, %1};" : "=l"(d) : "f"(x));
    return d;
}
__device__ __forceinline__ u64 pk2(float a, float b) {
    u64 d;
    asm("mov.b64 %0, {%1, %2};" : "=l"(d) : "f"(a), "f"(b));
    return d;
}
__device__ __forceinline__ float2 unpk(u64 a) {
    float2 r;
    asm("mov.b64 {%0, %1}, %2;" : "=f"(r.x), "=f"(r.y) : "l"(a));
    return r;
}
__device__ __forceinline__ float sigf(float v) {
    return 1.0f / (1.0f + __expf(-v));
}
__device__ __forceinline__ uint32_t smem_u32(const void* p) {
    uint32_t a;
    asm("{ .reg .u64 t; cvta.to.shared.u64 t, %1; cvt.u32.u64 %0, t; }" : "=r"(a) : "l"(p));
    return a;
}
__device__ __forceinline__ void cpa16(uint32_t saddr, const void* g) {
    asm volatile("cp.async.cg.shared.global [%0], [%1], 16;" :: "r"(saddr), "l"(g));
}
#define CPA_COMMIT() asm volatile("cp.async.commit_group;" ::: "memory")
#define CPA_WAIT1()  asm volatile("cp.async.wait_group 1;" ::: "memory")

// ---------------- init: h = features @ init_W + init_b ----------------
__global__ void init_kernel(const float* __restrict__ feat,
                            const float* __restrict__ W,
                            const float* __restrict__ b) {
    int i = blockIdx.x * blockDim.x + threadIdx.x;
    if (i >= ND) return;
    int n = i / DD;
    int d = i - n * DD;
    float f0 = feat[n * 4 + 0], f1 = feat[n * 4 + 1];
    float f2 = feat[n * 4 + 2], f3 = feat[n * 4 + 3];
    g_h[i] = b[d] + f0 * W[d] + f1 * W[DD + d] + f2 * W[2 * DD + d] + f3 * W[3 * DD + d];
}

// ---------------- one-time weight transpose: g_WT[m][d*300+j] = W[j*100+d] ----------------
__global__ void transpose_w_kernel(const float* __restrict__ A, const float* __restrict__ B,
                                   const float* __restrict__ C, const float* __restrict__ E) {
    int i = blockIdx.x * blockDim.x + threadIdx.x;
    if (i >= 30000) return;
    int d = i / TD, j = i - d * TD;
    int src = j * DD + d;
    g_WT[0][i] = A[src];
    g_WT[1][i] = B[src];
    g_WT[2][i] = C[src];
    g_WT[3][i] = E[src];
}

// ---------------- CSR build kernels ----------------
__global__ void zero_deg_kernel() {
    int i = blockIdx.x * blockDim.x + threadIdx.x;
    g_degF[i] = 0;
    g_degB[i] = 0;
}
__global__ void count_deg_kernel(const int* __restrict__ row, const int* __restrict__ col) {
    int e = blockIdx.x * blockDim.x + threadIdx.x;
    atomicAdd(&g_degF[row[e]], 1);
    atomicAdd(&g_degB[col[e]], 1);
}
__global__ void scan1_kernel() {
    __shared__ int s[1024];
    int b = blockIdx.x;
    const int* deg = (b < 128) ? g_degF : g_degB;
    int* rp = (b < 128) ? g_rpF : g_rpB;
    int base = (b & 127) * 1024;
    for (int i = threadIdx.x; i < 1024; i += blockDim.x) s[i] = deg[base + i];
    __syncthreads();
    if (threadIdx.x == 0) {
        int run = 0;
        for (int i = 0; i < 1024; i++) { int v = s[i]; s[i] = run; run += v; }
        g_bsum[b] = run;
    }
    __syncthreads();
    for (int i = threadIdx.x; i < 1024; i += blockDim.x) rp[base + i] = s[i];
}
__global__ void scan2_kernel() {
    int t = threadIdx.x;
    int base = t * 128;
    int run = 0;
    for (int i = 0; i < 128; i++) { int v = g_bsum[base + i]; g_bsum[base + i] = run; run += v; }
}
__global__ void scan3_kernel() {
    int i = blockIdx.x * blockDim.x + threadIdx.x;
    if (i < NN) {
        int v = g_rpF[i] + g_bsum[i >> 10];
        g_rpF[i] = v; g_fillF[i] = v;
    } else {
        int j = i - NN;
        int v = g_rpB[j] + g_bsum[128 + (j >> 10)];
        g_rpB[j] = v; g_fillB[j] = v;
    }
}
__global__ void fill_csr_kernel(const int* __restrict__ row, const int* __restrict__ col) {
    int e = blockIdx.x * blockDim.x + threadIdx.x;
    int r = row[e], c = col[e];
    int pF = atomicAdd(&g_fillF[r], 1);
    g_eF[pF] = c;
    int pB = atomicAdd(&g_fillB[c], 1);
    g_eB[pB] = r;
}

// ---------------- gather, thread-per-(node, float2 col): full lane utilization ----------
// NN*50 threads; thread handles one float2 of one node's msg row, 4-edge ILP.
__global__ void gather_kernel(const int* __restrict__ rp, const int* __restrict__ deg,
                              const int* __restrict__ eidx) {
    int gid = blockIdx.x * blockDim.x + threadIdx.x;     // < NN*50
    int node = gid / 50;
    int cp = gid - node * 50;                             // float2 index in row
    int s0 = __ldg(&rp[node]);
    int cnt = __ldg(&deg[node]);
    int c0 = 2 * cp;
    float2 acc = make_float2(0.f, 0.f);
    int i = 0;
#pragma unroll 1
    for (; i + 4 <= cnt; i += 4) {
        int sa = __ldg(&eidx[s0 + i]);
        int sb = __ldg(&eidx[s0 + i + 1]);
        int sc = __ldg(&eidx[s0 + i + 2]);
        int sd = __ldg(&eidx[s0 + i + 3]);
        float2 v0 = *(const float2*)&g_fm[(size_t)sa * DD + c0];
        float2 v1 = *(const float2*)&g_fm[(size_t)sb * DD + c0];
        float2 v2 = *(const float2*)&g_fm[(size_t)sc * DD + c0];
        float2 v3 = *(const float2*)&g_fm[(size_t)sd * DD + c0];
        acc.x += (v0.x + v1.x) + (v2.x + v3.x);
        acc.y += (v0.y + v1.y) + (v2.y + v3.y);
    }
#pragma unroll 1
    for (; i < cnt; i++) {
        int s = __ldg(&eidx[s0 + i]);
        float2 v = *(const float2*)&g_fm[(size_t)s * DD + c0];
        acc.x += v.x; acc.y += v.y;
    }
    *(float2*)&g_msg[(size_t)node * DD + c0] = acc;
}

// ---------------- persistent MLP (R10 passing form) ----------------
#define MLP_THREADS 256
#define MLP_NODES 64
#define HID 52
#define MLP_SMEM_FLOATS 26492

__global__ void __launch_bounds__(MLP_THREADS, 2)
mlp_kernel(const float* __restrict__ W1, const float* __restrict__ b1,
           const float* __restrict__ W2, const float* __restrict__ b2) {
    extern __shared__ float smem[];
    float* s_w1 = smem;
    float* s_w2 = smem + 5000;
    float* s_hid = smem + 10200;
    float* s_b2 = smem + 13528;
    float* s_b1 = smem + 13628;
    float* xb[2] = {smem + 13692, smem + 20092};
    uint32_t xaddr[2] = {smem_u32(xb[0]), smem_u32(xb[1])};

    int tid = threadIdx.x;
    int warp = tid >> 5, lane = tid & 31;
    int nb = warp * 8;
    int k0 = 4 * lane;
    bool act = lane < 25;
    const int NTILES = NN / MLP_NODES;   // 2048

#pragma unroll 1
    for (int i = tid; i < 1600; i += MLP_THREADS)
        cpa16(xaddr[0] + (uint32_t)i * 16u,
              (const void*)(((const float4*)g_h) + (size_t)blockIdx.x * 1600 + i));
    CPA_COMMIT();

    for (int i = tid; i < 5000; i += MLP_THREADS) s_w1[i] = W1[i];
    for (int i = tid; i < HID * DD; i += MLP_THREADS) s_w2[i] = (i < 5000) ? W2[i] : 0.f;
    if (tid < DD) s_b2[tid] = b2[tid];
    if (tid < DA) s_b1[tid] = b1[tid];
    if (lane == 25) {
#pragma unroll
        for (int nn = 0; nn < 8; nn++)
            *(float2*)&s_hid[(nb + nn) * HID + 50] = make_float2(0.f, 0.f);
    }

    int cur = 0;
#pragma unroll 1
    for (int tile = blockIdx.x; tile < NTILES; tile += PGRID) {
        int ntile = tile + PGRID;
        if (ntile < NTILES) {
#pragma unroll 1
            for (int i = tid; i < 1600; i += MLP_THREADS)
                cpa16(xaddr[cur ^ 1] + (uint32_t)i * 16u,
                      (const void*)(((const float4*)g_h) + (size_t)ntile * 1600 + i));
        }
        CPA_COMMIT();
        CPA_WAIT1();
        __syncthreads();

        int base = tile * MLP_NODES;
        const float* s_h = xb[cur];

        if (act) {
            int j0 = 2 * lane;
            u64 bias = pk2(s_b1[j0], s_b1[j0 + 1]);
            u64 acc[8];
#pragma unroll
            for (int nn = 0; nn < 8; nn++) acc[nn] = bias;
            const float* xp = s_h + nb * DD;
#pragma unroll 1
            for (int d4 = 0; d4 < DD; d4 += 4) {
                float4 xv[8];
#pragma unroll
                for (int nn = 0; nn < 8; nn++) xv[nn] = *(const float4*)&xp[nn * DD + d4];
#pragma unroll
                for (int dd = 0; dd < 4; dd++) {
                    u64 w = *(const u64*)&s_w1[(d4 + dd) * DA + j0];
#pragma unroll
                    for (int nn = 0; nn < 8; nn++)
                        acc[nn] = ffma2(w, dup2(((const float*)&xv[nn])[dd]), acc[nn]);
                }
            }
#pragma unroll
            for (int nn = 0; nn < 8; nn++) {
                float2 v = unpk(acc[nn]);
                *(float2*)&s_hid[(nb + nn) * HID + j0] =
                    make_float2(fmaxf(v.x, 0.f), fmaxf(v.y, 0.f));
            }
        }
        __syncwarp();

        if (act) {
            float4 bb = *(const float4*)&s_b2[k0];
            u64 a[8][2];
#pragma unroll
            for (int nn = 0; nn < 8; nn++) { a[nn][0] = pk2(bb.x, bb.y); a[nn][1] = pk2(bb.z, bb.w); }
            const float* hp = s_hid + nb * HID;
#pragma unroll 1
            for (int j4 = 0; j4 < HID; j4 += 4) {
                float4 hv[8];
#pragma unroll
                for (int nn = 0; nn < 8; nn++) hv[nn] = *(const float4*)&hp[nn * HID + j4];
#pragma unroll
                for (int dd = 0; dd < 4; dd++) {
                    ulonglong2 w = *(const ulonglong2*)&s_w2[(j4 + dd) * DD + k0];
#pragma unroll
                    for (int nn = 0; nn < 8; nn++) {
                        u64 v = dup2(((const float*)&hv[nn])[dd]);
                        a[nn][0] = ffma2(w.x, v, a[nn][0]);
                        a[nn][1] = ffma2(w.y, v, a[nn][1]);
                    }
                }
            }
#pragma unroll
            for (int nn = 0; nn < 8; nn++) {
                float2 p0 = unpk(a[nn][0]), p1 = unpk(a[nn][1]);
                *(float4*)&g_fm[(size_t)(base + nb + nn) * DD + k0] =
                    make_float4(p0.x, p0.y, p1.x, p1.y);
            }
        }
        __syncthreads();
        cur ^= 1;
    }
}

// ---------------- 6-stage GRU, full-matrix cp.async double buffer, 128-node tiles ------
// smem floats: wb0[10000] wb1[10000] xm[12800] xh[12800] bi[304] bh[304] = 46,208 -> 184,832 B
#define GRU_THREADS 512
#define GRU_NODES 128
#define GRU_SMEM_FLOATS 46208

__device__ __forceinline__ void prefetch_full(uint32_t dst, const float* __restrict__ srcWT,
                                              int ofs4, int tid) {
#pragma unroll 1
    for (int i = tid; i < 2500; i += GRU_THREADS) {
        int d = i / 25, q = i - (i / 25) * 25;
        cpa16(dst + (uint32_t)i * 16u, (const void*)((const float4*)srcWT + d * 75 + ofs4 + q));
    }
}

__global__ void __launch_bounds__(GRU_THREADS, 1)
gru_kernel(const float* __restrict__ WTih, const float* __restrict__ WThh,
           const float* __restrict__ bih, const float* __restrict__ bhh) {
    extern __shared__ float sm[];
    float* wb[2] = {sm, sm + 10000};
    float* s_xm = sm + 20000;
    float* s_xh = sm + 32800;
    float* s_bi = sm + 45600;
    float* s_bh = sm + 45904;
    uint32_t waddr[2] = {smem_u32(wb[0]), smem_u32(wb[1])};
    uint32_t xmaddr = smem_u32(s_xm);
    uint32_t xhaddr = smem_u32(s_xh);

    int tid = threadIdx.x;
    int base = blockIdx.x * GRU_NODES;
    int warp = tid >> 5, lane = tid & 31;
    int nb = warp * 8;
    int k0 = 4 * lane;
    bool act = lane < 25;

    // stage order: s0 ihr(xm), s1 hhr(xh)+R, s2 hhn(xh)+N1, s3 ihn(xm)+N2, s4 ihz(xm), s5 hhz(xh)+Z
    const float* srcs[6] = {WTih, WThh, WThh, WTih, WTih, WThh};
    const int ofsv[6] = {0, 0, 50, 50, 25, 25};

    // prologue: group0 = {xm, xh, W(s0)}, group1 = {W(s1)}
#pragma unroll 1
    for (int i = tid; i < 3200; i += GRU_THREADS) {
        cpa16(xmaddr + (uint32_t)i * 16u, (const void*)(((const float4*)g_msg) + base * 25 + i));
        cpa16(xhaddr + (uint32_t)i * 16u, (const void*)(((const float4*)g_h)   + base * 25 + i));
    }
    prefetch_full(waddr[0], WTih, 0, tid);
    CPA_COMMIT();
    prefetch_full(waddr[1], WThh, 0, tid);
    CPA_COMMIT();
    for (int i = tid; i < TD; i += GRU_THREADS) { s_bi[i] = bih[i]; s_bh[i] = bhh[i]; }

    u64 acc[8][2];
    float rg[8][4];

#define MATVEC_F(SXBASE, CW) do { \
        const float* xp_ = (SXBASE) + nb * DD; \
        const float* cw_ = (CW); \
        _Pragma("unroll 1") \
        for (int d4 = 0; d4 < DD; d4 += 4) { \
            float4 xv[8]; \
            _Pragma("unroll") \
            for (int nn = 0; nn < 8; nn++) xv[nn] = *(const float4*)&xp_[nn * DD + d4]; \
            _Pragma("unroll") \
            for (int dd = 0; dd < 4; dd++) { \
                ulonglong2 w = *(const ulonglong2*)&cw_[(d4 + dd) * DD + k0]; \
                _Pragma("unroll") \
                for (int nn = 0; nn < 8; nn++) { \
                    u64 v = dup2(((const float*)&xv[nn])[dd]); \
                    acc[nn][0] = ffma2(w.x, v, acc[nn][0]); \
                    acc[nn][1] = ffma2(w.y, v, acc[nn][1]); \
                } \
            } \
        } \
    } while (0)

#define ZERO_ACC() do { \
        _Pragma("unroll") \
        for (int nn = 0; nn < 8; nn++) { acc[nn][0] = 0ULL; acc[nn][1] = 0ULL; } \
    } while (0)

#define ST_PRE() CPA_WAIT1(); __syncthreads()
#define ST_POST(S) __syncthreads(); \
    { const int ns_ = (S) + 2; \
      if (ns_ < 6) prefetch_full(waddr[(S) & 1], srcs[ns_], ofsv[ns_], tid); } \
    CPA_COMMIT()

#define EPI_R() do { \
        float4 b1v = *(const float4*)&s_bi[k0]; \
        float4 b2v = *(const float4*)&s_bh[k0]; \
        _Pragma("unroll") \
        for (int nn = 0; nn < 8; nn++) { \
            float2 a0 = unpk(acc[nn][0]), a1 = unpk(acc[nn][1]); \
            rg[nn][0] = sigf(a0.x + b1v.x + b2v.x); \
            rg[nn][1] = sigf(a0.y + b1v.y + b2v.y); \
            rg[nn][2] = sigf(a1.x + b1v.z + b2v.z); \
            rg[nn][3] = sigf(a1.y + b1v.w + b2v.w); \
        } \
    } while (0)

#define EPI_N1() do { \
        float4 bn = *(const float4*)&s_bh[200 + k0]; \
        _Pragma("unroll") \
        for (int nn = 0; nn < 8; nn++) { \
            float2 a0 = unpk(acc[nn][0]), a1 = unpk(acc[nn][1]); \
            acc[nn][0] = pk2(rg[nn][0] * (a0.x + bn.x), rg[nn][1] * (a0.y + bn.y)); \
            acc[nn][1] = pk2(rg[nn][2] * (a1.x + bn.z), rg[nn][3] * (a1.y + bn.w)); \
        } \
    } while (0)

#define EPI_N2() do { \
        float4 bn = *(const float4*)&s_bi[200 + k0]; \
        _Pragma("unroll") \
        for (int nn = 0; nn < 8; nn++) { \
            float2 a0 = unpk(acc[nn][0]), a1 = unpk(acc[nn][1]); \
            rg[nn][0] = tanhf(a0.x + bn.x); \
            rg[nn][1] = tanhf(a0.y + bn.y); \
            rg[nn][2] = tanhf(a1.x + bn.z); \
            rg[nn][3] = tanhf(a1.y + bn.w); \
        } \
    } while (0)

#define EPI_Z() do { \
        float4 b1v = *(const float4*)&s_bi[100 + k0]; \
        float4 b2v = *(const float4*)&s_bh[100 + k0]; \
        _Pragma("unroll") \
        for (int nn = 0; nn < 8; nn++) { \
            float2 a0 = unpk(acc[nn][0]), a1 = unpk(acc[nn][1]); \
            float z0 = sigf(a0.x + b1v.x + b2v.x); \
            float z1 = sigf(a0.y + b1v.y + b2v.y); \
            float z2 = sigf(a1.x + b1v.z + b2v.z); \
            float z3 = sigf(a1.y + b1v.w + b2v.w); \
            float4 hv = *(const float4*)&s_xh[(nb + nn) * DD + k0]; \
            float4 o; \
            o.x = (1.f - z0) * rg[nn][0] + z0 * hv.x; \
            o.y = (1.f - z1) * rg[nn][1] + z1 * hv.y; \
            o.z = (1.f - z2) * rg[nn][2] + z2 * hv.z; \
            o.w = (1.f - z3) * rg[nn][3] + z3 * hv.w; \
            *(float4*)&g_h[(size_t)(base + nb + nn) * DD + k0] = o; \
        } \
    } while (0)

    ST_PRE(); if (act) { ZERO_ACC(); MATVEC_F(s_xm, wb[0]); } ST_POST(0);
    ST_PRE(); if (act) {             MATVEC_F(s_xh, wb[1]); EPI_R(); } ST_POST(1);
    ST_PRE(); if (act) { ZERO_ACC(); MATVEC_F(s_xh, wb[0]); EPI_N1(); } ST_POST(2);
    ST_PRE(); if (act) {             MATVEC_F(s_xm, wb[1]); EPI_N2(); } ST_POST(3);
    ST_PRE(); if (act) { ZERO_ACC(); MATVEC_F(s_xm, wb[0]); } ST_POST(4);
    ST_PRE(); if (act) {             MATVEC_F(s_xh, wb[1]); EPI_Z(); } ST_POST(5);

#undef MATVEC_F
#undef ZERO_ACC
#undef ST_PRE
#undef ST_POST
#undef EPI_R
#undef EPI_N1
#undef EPI_N2
#undef EPI_Z
}

// ---------------- classifier ----------------
__global__ void cls_kernel(const float* __restrict__ W1, const float* __restrict__ b1,
                           const float* __restrict__ W2, const float* __restrict__ b2,
                           float* __restrict__ out) {
    __shared__ float s_w1[DD * DC];
    __shared__ float s_b1[DC];
    __shared__ float s_w2[DC];
    __shared__ float s_row[8 * DD];

    int tid = threadIdx.x;
    int warp = tid >> 5, lane = tid & 31;
    int node = blockIdx.x * 8 + warp;

    for (int i = tid; i < DD * DC; i += blockDim.x) s_w1[i] = W1[i];
    if (tid < DC) { s_b1[tid] = b1[tid]; s_w2[tid] = W2[tid]; }
    __syncthreads();

    const float* hrow = &g_h[(size_t)node * DD];
    float* rbuf = &s_row[warp * DD];
    rbuf[lane] = hrow[lane];
    rbuf[lane + 32] = hrow[lane + 32];
    rbuf[lane + 64] = hrow[lane + 64];
    if (lane < 4) rbuf[lane + 96] = hrow[lane + 96];
    __syncwarp();

    float v = 0.f;
    if (lane < DC) {
        float acc = s_b1[lane];
#pragma unroll 4
        for (int d = 0; d < DD; d++) acc += rbuf[d] * s_w1[d * DC + lane];
        v = fmaxf(acc, 0.f) * s_w2[lane];
    }
#pragma unroll
    for (int off = 16; off > 0; off >>= 1) v += __shfl_down_sync(0xFFFFFFFFu, v, off);
    if (lane == 0) out[node] = v + b2[0];
}

// ---------------- host launch ----------------
extern "C" void kernel_launch(void* const* d_in, const int* in_sizes, int n_in,
                              void* d_out, int out_size) {
    const float* features = (const float*)d_in[0];
    const int* edge_row   = (const int*)d_in[1];
    const int* edge_col   = (const int*)d_in[2];
    const float* init_W = (const float*)d_in[3];
    const float* init_b = (const float*)d_in[4];
    const float* fmsg_W1 = (const float*)d_in[5];
    const float* fmsg_b1 = (const float*)d_in[6];
    const float* fmsg_W2 = (const float*)d_in[7];
    const float* fmsg_b2 = (const float*)d_in[8];
    const float* bmsg_W1 = (const float*)d_in[9];
    const float* bmsg_b1 = (const float*)d_in[10];
    const float* bmsg_W2 = (const float*)d_in[11];
    const float* bmsg_b2 = (const float*)d_in[12];
    const float* fgru_Wih = (const float*)d_in[13];
    const float* fgru_Whh = (const float*)d_in[14];
    const float* fgru_bih = (const float*)d_in[15];
    const float* fgru_bhh = (const float*)d_in[16];
    const float* bgru_Wih = (const float*)d_in[17];
    const float* bgru_Whh = (const float*)d_in[18];
    const float* bgru_bih = (const float*)d_in[19];
    const float* bgru_bhh = (const float*)d_in[20];
    const float* cls_W1 = (const float*)d_in[21];
    const float* cls_b1 = (const float*)d_in[22];
    const float* cls_W2 = (const float*)d_in[23];
    const float* cls_b2 = (const float*)d_in[24];
    float* out = (float*)d_out;

    const int mlp_smem = MLP_SMEM_FLOATS * 4;   // 105,968 B
    const int gru_smem = GRU_SMEM_FLOATS * 4;   // 184,832 B
    cudaFuncSetAttribute((const void*)mlp_kernel,
                         cudaFuncAttributeMaxDynamicSharedMemorySize, mlp_smem);
    cudaFuncSetAttribute((const void*)gru_kernel,
                         cudaFuncAttributeMaxDynamicSharedMemorySize, gru_smem);

    // resolve device-global scratch addresses
    float* wt_base = nullptr;
    cudaGetSymbolAddress((void**)&wt_base, g_WT);
    const float* fWihT = wt_base;
    const float* fWhhT = wt_base + 30000;
    const float* bWihT = wt_base + 60000;
    const float* bWhhT = wt_base + 90000;
    int *rpF, *rpB, *degF, *degB, *eF, *eB;
    cudaGetSymbolAddress((void**)&rpF, g_rpF);
    cudaGetSymbolAddress((void**)&rpB, g_rpB);
    cudaGetSymbolAddress((void**)&degF, g_degF);
    cudaGetSymbolAddress((void**)&degB, g_degB);
    cudaGetSymbolAddress((void**)&eF, g_eF);
    cudaGetSymbolAddress((void**)&eB, g_eB);

    init_kernel<<<(ND + 255) / 256, 256>>>(features, init_W, init_b);
    transpose_w_kernel<<<(30000 + 255) / 256, 256>>>(fgru_Wih, fgru_Whh, bgru_Wih, bgru_Whh);

    // CSR build (edges constant across rounds)
    zero_deg_kernel<<<NN / 256, 256>>>();
    count_deg_kernel<<<EE / 256, 256>>>(edge_row, edge_col);
    scan1_kernel<<<256, 256>>>();
    scan2_kernel<<<1, 2>>>();
    scan3_kernel<<<(2 * NN) / 256, 256>>>();
    fill_csr_kernel<<<EE / 256, 256>>>(edge_row, edge_col);

    const int gru_blocks = NN / GRU_NODES;        // 1024
    const int gat_blocks = (NN * 50) / 256;       // 25600

    for (int r = 0; r < 20; r++) {
        // forward: msg[row] = sum fm[col]
        mlp_kernel<<<PGRID, MLP_THREADS, mlp_smem>>>(fmsg_W1, fmsg_b1, fmsg_W2, fmsg_b2);
        gather_kernel<<<gat_blocks, 256>>>(rpF, degF, eF);
        gru_kernel<<<gru_blocks, GRU_THREADS, gru_smem>>>(fWihT, fWhhT, fgru_bih, fgru_bhh);
        // backward: msg[col] = sum bm[row]
        mlp_kernel<<<PGRID, MLP_THREADS, mlp_smem>>>(bmsg_W1, bmsg_b1, bmsg_W2, bmsg_b2);
        gather_kernel<<<gat_blocks, 256>>>(rpB, degB, eB);
        gru_kernel<<<gru_blocks, GRU_THREADS, gru_smem>>>(bWihT, bWhhT, bgru_bih, bgru_bhh);
    }

    cls_kernel<<<NN / 8, 256>>>(cls_W1, cls_b1, cls_W2, cls_b2, out);
    (void)in_sizes; (void)n_in; (void)out_size;
}